// round 1
// baseline (speedup 1.0000x reference)
#include <cuda_runtime.h>

// Problem constants
#define BATCH 2
#define SEQ   2048
#define DIM   1024
#define NH    16
#define HD    64
#define MROWS (BATCH * SEQ)   // 4096

// Scratch (allocation-free rule: __device__ globals)
__device__ float g_q[BATCH * NH * SEQ * HD];   // [B,H,S,hd]
__device__ float g_k[BATCH * NH * SEQ * HD];
__device__ float g_v[BATCH * NH * SEQ * HD];
__device__ float g_h[MROWS * DIM];             // [B,S,D] attention output

// ---------------------------------------------------------------------------
// C = A @ B^T.  A: [M,K] row-major, Bm: [N,K] row-major.
// BM=BN=128, BK=16, 256 threads, 8x8 per-thread tile.
// MODE 0: scatter epilogue into g_q/g_k/g_v ([B,H,S,hd] layout)
// MODE 1: plain row-major store to C with leading dim Nld
// ---------------------------------------------------------------------------
template <int MODE>
__global__ __launch_bounds__(256) void sgemm_nt(const float* __restrict__ A,
                                                const float* __restrict__ Bm,
                                                float* __restrict__ C,
                                                int K, int Nld) {
    __shared__ float As[16][128];
    __shared__ float Bs[16][128];

    const int tid = threadIdx.x;
    const int m0 = blockIdx.y * 128;
    const int n0 = blockIdx.x * 128;
    const float* Ap = A + (size_t)m0 * K;
    const float* Bp = Bm + (size_t)n0 * K;

    const int tx = tid & 15;        // 0..15 -> n direction
    const int ty = tid >> 4;        // 0..15 -> m direction

    float acc[8][8];
#pragma unroll
    for (int i = 0; i < 8; i++)
#pragma unroll
        for (int j = 0; j < 8; j++) acc[i][j] = 0.0f;

    for (int k0 = 0; k0 < K; k0 += 16) {
#pragma unroll
        for (int i = 0; i < 2; i++) {
            int lin = tid + i * 256;
            int row = lin >> 2;          // 0..127
            int c4  = (lin & 3) * 4;     // 0,4,8,12
            float4 a = *(const float4*)(Ap + (size_t)row * K + k0 + c4);
            As[c4 + 0][row] = a.x; As[c4 + 1][row] = a.y;
            As[c4 + 2][row] = a.z; As[c4 + 3][row] = a.w;
            float4 b = *(const float4*)(Bp + (size_t)row * K + k0 + c4);
            Bs[c4 + 0][row] = b.x; Bs[c4 + 1][row] = b.y;
            Bs[c4 + 2][row] = b.z; Bs[c4 + 3][row] = b.w;
        }
        __syncthreads();

#pragma unroll
        for (int k = 0; k < 16; k++) {
            float ra[8], rb[8];
            *(float4*)&ra[0] = *(const float4*)&As[k][ty * 8];
            *(float4*)&ra[4] = *(const float4*)&As[k][ty * 8 + 4];
            *(float4*)&rb[0] = *(const float4*)&Bs[k][tx * 8];
            *(float4*)&rb[4] = *(const float4*)&Bs[k][tx * 8 + 4];
#pragma unroll
            for (int i = 0; i < 8; i++)
#pragma unroll
                for (int j = 0; j < 8; j++)
                    acc[i][j] = fmaf(ra[i], rb[j], acc[i][j]);
        }
        __syncthreads();
    }

    if (MODE == 0) {
        // scatter into q/k/v with [B,H,S,hd] layout
#pragma unroll
        for (int i = 0; i < 8; i++) {
            int m = m0 + ty * 8 + i;
            int b = m >> 11;            // /SEQ
            int s = m & (SEQ - 1);
#pragma unroll
            for (int j = 0; j < 8; j++) {
                int n = n0 + tx * 8 + j;
                int sel    = n >> 10;          // 0:q 1:k 2:v
                int within = n & (DIM - 1);
                int head   = within >> 6;
                int dcol   = within & (HD - 1);
                size_t idx = (((size_t)(b * NH + head) * SEQ) + s) * HD + dcol;
                float val = acc[i][j];
                if (sel == 0)      g_q[idx] = val;
                else if (sel == 1) g_k[idx] = val;
                else               g_v[idx] = val;
            }
        }
    } else {
#pragma unroll
        for (int i = 0; i < 8; i++) {
            int m = m0 + ty * 8 + i;
            float* crow = C + (size_t)m * Nld + n0 + tx * 8;
#pragma unroll
            for (int j = 0; j < 8; j++) crow[j] = acc[i][j];
        }
    }
}

// ---------------------------------------------------------------------------
// Flash attention, causal. One CTA per (b*h, 64-query tile).
// 256 threads. K-tiles of 32. Online softmax. Writes H in [B,S,D] layout.
// ---------------------------------------------------------------------------
__global__ __launch_bounds__(256) void attn_kernel() {
    __shared__ float Qs[64][68];
    __shared__ float Ks[32][68];
    __shared__ float Vs[32][64];
    __shared__ float Ss[64][33];
    __shared__ float m_s[64], l_s[64], scale_s[64];

    const int tid = threadIdx.x;
    const int q0  = blockIdx.x * 64;
    const int bh  = blockIdx.y;          // b*NH + h
    const int b   = bh >> 4;
    const int h   = bh & 15;

    const float* Qp = g_q + ((size_t)bh * SEQ + q0) * HD;
    const float* Kp = g_k + (size_t)bh * SEQ * HD;
    const float* Vp = g_v + (size_t)bh * SEQ * HD;

    // load Q tile: 64x64 floats
#pragma unroll
    for (int i = 0; i < 4; i++) {
        int lin = tid + i * 256;
        int row = lin >> 4;              // 0..63
        int c4  = (lin & 15) * 4;        // 0..60
        *(float4*)&Qs[row][c4] = *(const float4*)(Qp + (size_t)row * HD + c4);
    }
    if (tid < 64) { m_s[tid] = -1e30f; l_s[tid] = 0.0f; }

    const int r0 = (tid >> 4) * 4;       // 4 query rows per thread
    const int c0 = (tid & 15) * 2;       // 2 key cols (score phase)
    const int d0 = (tid & 15) * 4;       // 4 head dims (PV phase)

    float oacc[4][4];
#pragma unroll
    for (int i = 0; i < 4; i++)
#pragma unroll
        for (int j = 0; j < 4; j++) oacc[i][j] = 0.0f;

    const int kend = q0 + 64;            // causal bound (exclusive)
    for (int k0 = 0; k0 < kend; k0 += 32) {
        __syncthreads();                 // protect K/V/Ss reuse
        // load K,V tiles: 32x64 each
#pragma unroll
        for (int i = 0; i < 2; i++) {
            int lin = tid + i * 256;
            int row = lin >> 4;
            int c4  = (lin & 15) * 4;
            *(float4*)&Ks[row][c4] = *(const float4*)(Kp + (size_t)(k0 + row) * HD + c4);
            *(float4*)&Vs[row][c4] = *(const float4*)(Vp + (size_t)(k0 + row) * HD + c4);
        }
        __syncthreads();

        // scores: 4 rows x 2 cols per thread
        float sc[4][2];
#pragma unroll
        for (int i = 0; i < 4; i++) { sc[i][0] = 0.0f; sc[i][1] = 0.0f; }
#pragma unroll
        for (int d = 0; d < 64; d += 4) {
            float4 kv0 = *(const float4*)&Ks[c0][d];
            float4 kv1 = *(const float4*)&Ks[c0 + 1][d];
#pragma unroll
            for (int i = 0; i < 4; i++) {
                float4 qv = *(const float4*)&Qs[r0 + i][d];
                sc[i][0] = fmaf(qv.x, kv0.x, sc[i][0]);
                sc[i][0] = fmaf(qv.y, kv0.y, sc[i][0]);
                sc[i][0] = fmaf(qv.z, kv0.z, sc[i][0]);
                sc[i][0] = fmaf(qv.w, kv0.w, sc[i][0]);
                sc[i][1] = fmaf(qv.x, kv1.x, sc[i][1]);
                sc[i][1] = fmaf(qv.y, kv1.y, sc[i][1]);
                sc[i][1] = fmaf(qv.z, kv1.z, sc[i][1]);
                sc[i][1] = fmaf(qv.w, kv1.w, sc[i][1]);
            }
        }
#pragma unroll
        for (int i = 0; i < 4; i++) {
            int qg = q0 + r0 + i;
#pragma unroll
            for (int j = 0; j < 2; j++) {
                int kg = k0 + c0 + j;
                Ss[r0 + i][c0 + j] = (kg <= qg) ? sc[i][j] * 0.125f : -1e30f;
            }
        }
        __syncthreads();

        // online softmax, one thread per row
        if (tid < 64) {
            int r = tid;
            float mo = m_s[r];
            float mn = mo;
#pragma unroll
            for (int c = 0; c < 32; c++) mn = fmaxf(mn, Ss[r][c]);
            float sc_ = __expf(mo - mn);
            float l = l_s[r] * sc_;
#pragma unroll
            for (int c = 0; c < 32; c++) {
                float p = __expf(Ss[r][c] - mn);
                Ss[r][c] = p;
                l += p;
            }
            m_s[r] = mn; l_s[r] = l; scale_s[r] = sc_;
        }
        __syncthreads();

        // O = O*scale + P @ V
#pragma unroll
        for (int i = 0; i < 4; i++) {
            float s = scale_s[r0 + i];
#pragma unroll
            for (int j = 0; j < 4; j++) oacc[i][j] *= s;
        }
#pragma unroll
        for (int c = 0; c < 32; c++) {
            float4 v = *(const float4*)&Vs[c][d0];
#pragma unroll
            for (int i = 0; i < 4; i++) {
                float p = Ss[r0 + i][c];
                oacc[i][0] = fmaf(p, v.x, oacc[i][0]);
                oacc[i][1] = fmaf(p, v.y, oacc[i][1]);
                oacc[i][2] = fmaf(p, v.z, oacc[i][2]);
                oacc[i][3] = fmaf(p, v.w, oacc[i][3]);
            }
        }
    }

    // write normalized output into [B,S,D] layout
#pragma unroll
    for (int i = 0; i < 4; i++) {
        float inv = 1.0f / l_s[r0 + i];
        int s_glob = q0 + r0 + i;
        float* dst = g_h + ((size_t)b * SEQ + s_glob) * DIM + h * HD + d0;
        dst[0] = oacc[i][0] * inv;
        dst[1] = oacc[i][1] * inv;
        dst[2] = oacc[i][2] * inv;
        dst[3] = oacc[i][3] * inv;
    }
}

// ---------------------------------------------------------------------------
extern "C" void kernel_launch(void* const* d_in, const int* in_sizes, int n_in,
                              void* d_out, int out_size) {
    const float* x     = (const float*)d_in[0];   // [B,S,D]
    const float* w_qkv = (const float*)d_in[1];   // [3D, D]
    const float* w_o   = (const float*)d_in[2];   // [D, D]
    float* out = (float*)d_out;                   // [B,S,D]

    // QKV projection: [4096,1024] @ [3072,1024]^T, scatter to q/k/v
    sgemm_nt<0><<<dim3(3 * DIM / 128, MROWS / 128), 256>>>(x, w_qkv, nullptr, DIM, 0);

    // Causal flash attention -> g_h [B,S,D]
    attn_kernel<<<dim3(SEQ / 64, BATCH * NH), 256>>>();

    // Output projection: [4096,1024] @ [1024,1024]^T -> d_out
    float* hptr = nullptr;
    cudaGetSymbolAddress((void**)&hptr, g_h);
    sgemm_nt<1><<<dim3(DIM / 128, MROWS / 128), 256>>>(hptr, w_o, out, DIM, DIM);
}

// round 4
// speedup vs baseline: 1.5372x; 1.5372x over previous
#include <cuda_runtime.h>

// Problem constants
#define BATCH 2
#define SEQ   2048
#define DIM   1024
#define NH    16
#define HD    64
#define MROWS (BATCH * SEQ)   // 4096

// Scratch (allocation-free rule: __device__ globals)
__device__ float g_q[BATCH * NH * SEQ * HD];   // [B,H,S,hd]
__device__ float g_k[BATCH * NH * SEQ * HD];
__device__ float g_v[BATCH * NH * SEQ * HD];
__device__ float g_h[MROWS * DIM];             // [B,S,D] attention output

__device__ __forceinline__ float to_tf32(float x) {
    unsigned u;
    asm("cvt.rna.tf32.f32 %0, %1;" : "=r"(u) : "f"(x));
    return __uint_as_float(u);
}

__device__ __forceinline__ void mma_tf32(float* c, const unsigned* a, const unsigned* b) {
    asm volatile(
        "mma.sync.aligned.m16n8k8.row.col.f32.tf32.tf32.f32 "
        "{%0,%1,%2,%3}, {%4,%5,%6,%7}, {%8,%9}, {%0,%1,%2,%3};"
        : "+f"(c[0]), "+f"(c[1]), "+f"(c[2]), "+f"(c[3])
        : "r"(a[0]), "r"(a[1]), "r"(a[2]), "r"(a[3]), "r"(b[0]), "r"(b[1]));
}

// ---------------------------------------------------------------------------
// C = A @ B^T via tf32 mma.sync.  A: [M,K] rm, Bm: [N,K] rm.
// CTA tile 128x128, BK=32, 256 threads = 8 warps (2m x 4n), warp tile 64x32.
// MODE 0: scatter epilogue into g_q/g_k/g_v ([B,H,S,hd]); MODE 1: row-major C.
// ---------------------------------------------------------------------------
template <int MODE>
__global__ __launch_bounds__(256) void gemm_tf32(const float* __restrict__ A,
                                                 const float* __restrict__ Bm,
                                                 float* __restrict__ C,
                                                 int K, int Nld) {
    __shared__ float As[128][36];   // padded: 36r mod 32 -> conflict-free frags
    __shared__ float Bs[128][36];

    const int tid  = threadIdx.x;
    const int m0   = blockIdx.y * 128;
    const int n0   = blockIdx.x * 128;
    const int warp = tid >> 5;
    const int lane = tid & 31;
    const int wm   = (warp & 1) * 64;   // warp m offset
    const int wn   = (warp >> 1) * 32;  // warp n offset
    const int g    = lane >> 2;         // groupID
    const int tg   = lane & 3;          // threadID_in_group

    float acc[4][4][4];
#pragma unroll
    for (int mt = 0; mt < 4; mt++)
#pragma unroll
        for (int nt = 0; nt < 4; nt++)
#pragma unroll
            for (int i = 0; i < 4; i++) acc[mt][nt][i] = 0.0f;

    // gmem tile loads: 128 rows x 32 cols, 16 floats (4 float4) per thread
    const int lrow = tid >> 1;
    const int lcol = (tid & 1) * 16;
    const float* ap = A  + (size_t)(m0 + lrow) * K + lcol;
    const float* bp = Bm + (size_t)(n0 + lrow) * K + lcol;

    float4 pa[4], pb[4];
#pragma unroll
    for (int i = 0; i < 4; i++) { pa[i] = *(const float4*)(ap + i * 4); pb[i] = *(const float4*)(bp + i * 4); }

    for (int k0 = 0; k0 < K; k0 += 32) {
        // store current tile (convert to tf32 once, reused by all warps)
#pragma unroll
        for (int i = 0; i < 4; i++) {
            float4 a = pa[i], b = pb[i];
            a.x = to_tf32(a.x); a.y = to_tf32(a.y); a.z = to_tf32(a.z); a.w = to_tf32(a.w);
            b.x = to_tf32(b.x); b.y = to_tf32(b.y); b.z = to_tf32(b.z); b.w = to_tf32(b.w);
            *(float4*)&As[lrow][lcol + i * 4] = a;
            *(float4*)&Bs[lrow][lcol + i * 4] = b;
        }
        __syncthreads();

        // prefetch next tile
        if (k0 + 32 < K) {
#pragma unroll
            for (int i = 0; i < 4; i++) {
                pa[i] = *(const float4*)(ap + k0 + 32 + i * 4);
                pb[i] = *(const float4*)(bp + k0 + 32 + i * 4);
            }
        }

#pragma unroll
        for (int kt = 0; kt < 4; kt++) {
            const int kc = kt * 8 + tg;
            unsigned fa[4][4], fb[4][2];
#pragma unroll
            for (int mt = 0; mt < 4; mt++) {
                const int r = wm + mt * 16 + g;
                fa[mt][0] = __float_as_uint(As[r][kc]);
                fa[mt][1] = __float_as_uint(As[r + 8][kc]);
                fa[mt][2] = __float_as_uint(As[r][kc + 4]);
                fa[mt][3] = __float_as_uint(As[r + 8][kc + 4]);
            }
#pragma unroll
            for (int nt = 0; nt < 4; nt++) {
                const int r = wn + nt * 8 + g;
                fb[nt][0] = __float_as_uint(Bs[r][kc]);
                fb[nt][1] = __float_as_uint(Bs[r][kc + 4]);
            }
#pragma unroll
            for (int mt = 0; mt < 4; mt++)
#pragma unroll
                for (int nt = 0; nt < 4; nt++)
                    mma_tf32(acc[mt][nt], fa[mt], fb[nt]);
        }
        __syncthreads();
    }

    // epilogue: c0=(g,2tg) c1=(g,2tg+1) c2=(g+8,2tg) c3=(g+8,2tg+1)
#pragma unroll
    for (int mt = 0; mt < 4; mt++) {
#pragma unroll
        for (int nt = 0; nt < 4; nt++) {
#pragma unroll
            for (int half = 0; half < 2; half++) {
                const int m = m0 + wm + mt * 16 + g + half * 8;
                const int n = n0 + wn + nt * 8 + tg * 2;
                float2 val = make_float2(acc[mt][nt][half * 2], acc[mt][nt][half * 2 + 1]);
                if (MODE == 0) {
                    const int b = m >> 11;
                    const int s = m & (SEQ - 1);
                    const int sel    = n >> 10;
                    const int within = n & (DIM - 1);
                    const int head   = within >> 6;
                    const int dcol   = within & (HD - 1);
                    const size_t idx = (((size_t)(b * NH + head) * SEQ) + s) * HD + dcol;
                    if (sel == 0)      *(float2*)&g_q[idx] = val;
                    else if (sel == 1) *(float2*)&g_k[idx] = val;
                    else               *(float2*)&g_v[idx] = val;
                } else {
                    *(float2*)&C[(size_t)m * Nld + n] = val;
                }
            }
        }
    }
}

// ---------------------------------------------------------------------------
// Flash attention, causal. Q tile 128, K tile 64, 256 threads.
// Per-thread 8x4 tiles for scores and PV. Softmax: 2 threads per row.
// Dynamic smem (~104KB), up to 2 CTAs/SM.
// ---------------------------------------------------------------------------
extern __shared__ float sm_attn[];

__global__ __launch_bounds__(256) void attn_kernel() {
    float (*Qs)[68] = (float(*)[68])sm_attn;                 // 128x68
    float (*Ks)[68] = (float(*)[68])(sm_attn + 8704);        // 64x68
    float (*Vs)[64] = (float(*)[64])(sm_attn + 13056);       // 64x64
    float (*Ss)[68] = (float(*)[68])(sm_attn + 17152);       // 128x68
    float* m_s  = sm_attn + 25856;
    float* l_s  = m_s + 128;
    float* sc_s = l_s + 128;

    const int tid = threadIdx.x;
    const int q0  = ((int)gridDim.x - 1 - (int)blockIdx.x) * 128;  // big tiles first
    const int bh  = blockIdx.y;
    const int b   = bh >> 4;
    const int h   = bh & 15;

    const float* Qp = g_q + ((size_t)bh * SEQ + q0) * HD;
    const float* Kp = g_k + (size_t)bh * SEQ * HD;
    const float* Vp = g_v + (size_t)bh * SEQ * HD;

    const int rowg = tid >> 4;           // 0..15
    const int colg = tid & 15;           // 0..15
    const int c4   = colg * 4;

    // load Q tile 128x64
#pragma unroll
    for (int i = 0; i < 8; i++) {
        const int row = i * 16 + rowg;
        *(float4*)&Qs[row][c4] = *(const float4*)(Qp + (size_t)row * HD + c4);
    }
    if (tid < 128) { m_s[tid] = -1e30f; l_s[tid] = 0.0f; }

    const int r0 = rowg * 8;             // 8 query rows per thread
    const int d0 = c4;                   // 4 cols (scores: key cols; PV: head dims)

    float oacc[8][4];
#pragma unroll
    for (int i = 0; i < 8; i++)
#pragma unroll
        for (int j = 0; j < 4; j++) oacc[i][j] = 0.0f;

    const int kend = q0 + 128;
    for (int k0 = 0; k0 < kend; k0 += 64) {
        __syncthreads();                 // protect K/V/Ss reuse
#pragma unroll
        for (int i = 0; i < 4; i++) {
            const int row = i * 16 + rowg;
            *(float4*)&Ks[row][c4] = *(const float4*)(Kp + (size_t)(k0 + row) * HD + c4);
            *(float4*)&Vs[row][c4] = *(const float4*)(Vp + (size_t)(k0 + row) * HD + c4);
        }
        __syncthreads();

        // scores: 8 rows x 4 key-cols per thread
        float sc[8][4];
#pragma unroll
        for (int i = 0; i < 8; i++)
#pragma unroll
            for (int j = 0; j < 4; j++) sc[i][j] = 0.0f;

#pragma unroll 4
        for (int d = 0; d < 64; d += 4) {
            float4 kf[4];
#pragma unroll
            for (int j = 0; j < 4; j++) kf[j] = *(const float4*)&Ks[d0 + j][d];
#pragma unroll
            for (int i = 0; i < 8; i++) {
                float4 qf = *(const float4*)&Qs[r0 + i][d];
#pragma unroll
                for (int j = 0; j < 4; j++) {
                    sc[i][j] = fmaf(qf.x, kf[j].x, sc[i][j]);
                    sc[i][j] = fmaf(qf.y, kf[j].y, sc[i][j]);
                    sc[i][j] = fmaf(qf.z, kf[j].z, sc[i][j]);
                    sc[i][j] = fmaf(qf.w, kf[j].w, sc[i][j]);
                }
            }
        }
#pragma unroll
        for (int i = 0; i < 8; i++) {
            const int qg = q0 + r0 + i;
#pragma unroll
            for (int j = 0; j < 4; j++) {
                const int kg = k0 + d0 + j;
                Ss[r0 + i][d0 + j] = (kg <= qg) ? sc[i][j] * 0.125f : -1e30f;
            }
        }
        __syncthreads();

        // online softmax: 2 threads per row, 32 cols each
        {
            const int r  = tid >> 1;
            const int co = (tid & 1) * 32;
            float mx = -1e30f;
#pragma unroll
            for (int c = 0; c < 32; c++) mx = fmaxf(mx, Ss[r][co + c]);
            mx = fmaxf(mx, __shfl_xor_sync(0xffffffffu, mx, 1));
            const float mo = m_s[r];
            const float mn = fmaxf(mo, mx);
            float l = 0.0f;
#pragma unroll
            for (int c = 0; c < 32; c++) {
                const float p = __expf(Ss[r][co + c] - mn);
                Ss[r][co + c] = p;
                l += p;
            }
            l += __shfl_xor_sync(0xffffffffu, l, 1);
            if ((tid & 1) == 0) {
                const float scl = __expf(mo - mn);
                l_s[r] = l_s[r] * scl + l;
                m_s[r] = mn;
                sc_s[r] = scl;
            }
        }
        __syncthreads();

        // O = O*scale + P @ V  (8 rows x 4 dims per thread)
#pragma unroll
        for (int i = 0; i < 8; i++) {
            const float s = sc_s[r0 + i];
#pragma unroll
            for (int j = 0; j < 4; j++) oacc[i][j] *= s;
        }
#pragma unroll 4
        for (int c = 0; c < 64; c += 4) {
            float4 vf[4];
#pragma unroll
            for (int j = 0; j < 4; j++) vf[j] = *(const float4*)&Vs[c + j][d0];
#pragma unroll
            for (int i = 0; i < 8; i++) {
                float4 pf = *(const float4*)&Ss[r0 + i][c];
                oacc[i][0] = fmaf(pf.x, vf[0].x, oacc[i][0]);
                oacc[i][0] = fmaf(pf.y, vf[1].x, oacc[i][0]);
                oacc[i][0] = fmaf(pf.z, vf[2].x, oacc[i][0]);
                oacc[i][0] = fmaf(pf.w, vf[3].x, oacc[i][0]);
                oacc[i][1] = fmaf(pf.x, vf[0].y, oacc[i][1]);
                oacc[i][1] = fmaf(pf.y, vf[1].y, oacc[i][1]);
                oacc[i][1] = fmaf(pf.z, vf[2].y, oacc[i][1]);
                oacc[i][1] = fmaf(pf.w, vf[3].y, oacc[i][1]);
                oacc[i][2] = fmaf(pf.x, vf[0].z, oacc[i][2]);
                oacc[i][2] = fmaf(pf.y, vf[1].z, oacc[i][2]);
                oacc[i][2] = fmaf(pf.z, vf[2].z, oacc[i][2]);
                oacc[i][2] = fmaf(pf.w, vf[3].z, oacc[i][2]);
                oacc[i][3] = fmaf(pf.x, vf[0].w, oacc[i][3]);
                oacc[i][3] = fmaf(pf.y, vf[1].w, oacc[i][3]);
                oacc[i][3] = fmaf(pf.z, vf[2].w, oacc[i][3]);
                oacc[i][3] = fmaf(pf.w, vf[3].w, oacc[i][3]);
            }
        }
    }

    // write normalized output [B,S,D]
#pragma unroll
    for (int i = 0; i < 8; i++) {
        const int r = r0 + i;
        const float inv = 1.0f / l_s[r];
        const int s_glob = q0 + r;
        float4 o = make_float4(oacc[i][0] * inv, oacc[i][1] * inv,
                               oacc[i][2] * inv, oacc[i][3] * inv);
        *(float4*)(g_h + ((size_t)b * SEQ + s_glob) * DIM + h * HD + d0) = o;
    }
}

// ---------------------------------------------------------------------------
extern "C" void kernel_launch(void* const* d_in, const int* in_sizes, int n_in,
                              void* d_out, int out_size) {
    const float* x     = (const float*)d_in[0];   // [B,S,D]
    const float* w_qkv = (const float*)d_in[1];   // [3D, D]
    const float* w_o   = (const float*)d_in[2];   // [D, D]
    float* out = (float*)d_out;                   // [B,S,D]

    const int ATTN_SMEM = (25856 + 3 * 128) * 4;  // ~104.4 KB
    cudaFuncSetAttribute(attn_kernel, cudaFuncAttributeMaxDynamicSharedMemorySize, ATTN_SMEM);

    // QKV projection: [4096,1024] @ [3072,1024]^T, scatter to q/k/v (tf32 mma)
    gemm_tf32<0><<<dim3(3 * DIM / 128, MROWS / 128), 256>>>(x, w_qkv, nullptr, DIM, 0);

    // Causal flash attention -> g_h [B,S,D]
    attn_kernel<<<dim3(SEQ / 128, BATCH * NH), 256, ATTN_SMEM>>>();

    // Output projection: [4096,1024] @ [1024,1024]^T -> d_out (tf32 mma)
    float* hptr = nullptr;
    cudaGetSymbolAddress((void**)&hptr, g_h);
    gemm_tf32<1><<<dim3(DIM / 128, MROWS / 128), 256>>>(hptr, w_o, out, DIM, DIM);
}

// round 5
// speedup vs baseline: 2.8738x; 1.8695x over previous
#include <cuda_runtime.h>

// Problem constants
#define BATCH 2
#define SEQ   2048
#define DIM   1024
#define NH    16
#define HD    64
#define MROWS (BATCH * SEQ)   // 4096

// Scratch (allocation-free rule: __device__ globals)
__device__ float g_q[BATCH * NH * SEQ * HD];   // [B,H,S,hd]
__device__ float g_k[BATCH * NH * SEQ * HD];
__device__ float g_v[BATCH * NH * SEQ * HD];
__device__ float g_h[MROWS * DIM];             // [B,S,D] attention output

__device__ __forceinline__ float to_tf32(float x) {
    unsigned u;
    asm("cvt.rna.tf32.f32 %0, %1;" : "=r"(u) : "f"(x));
    return __uint_as_float(u);
}
__device__ __forceinline__ unsigned to_tf32u(float x) {
    unsigned u;
    asm("cvt.rna.tf32.f32 %0, %1;" : "=r"(u) : "f"(x));
    return u;
}

__device__ __forceinline__ void mma_tf32(float* c, const unsigned* a, const unsigned* b) {
    asm volatile(
        "mma.sync.aligned.m16n8k8.row.col.f32.tf32.tf32.f32 "
        "{%0,%1,%2,%3}, {%4,%5,%6,%7}, {%8,%9}, {%0,%1,%2,%3};"
        : "+f"(c[0]), "+f"(c[1]), "+f"(c[2]), "+f"(c[3])
        : "r"(a[0]), "r"(a[1]), "r"(a[2]), "r"(a[3]), "r"(b[0]), "r"(b[1]));
}

// ---------------------------------------------------------------------------
// C = A @ B^T via tf32 mma.sync.  (identical to R4 passing version)
// ---------------------------------------------------------------------------
template <int MODE>
__global__ __launch_bounds__(256) void gemm_tf32(const float* __restrict__ A,
                                                 const float* __restrict__ Bm,
                                                 float* __restrict__ C,
                                                 int K, int Nld) {
    __shared__ float As[128][36];
    __shared__ float Bs[128][36];

    const int tid  = threadIdx.x;
    const int m0   = blockIdx.y * 128;
    const int n0   = blockIdx.x * 128;
    const int warp = tid >> 5;
    const int lane = tid & 31;
    const int wm   = (warp & 1) * 64;
    const int wn   = (warp >> 1) * 32;
    const int g    = lane >> 2;
    const int tg   = lane & 3;

    float acc[4][4][4];
#pragma unroll
    for (int mt = 0; mt < 4; mt++)
#pragma unroll
        for (int nt = 0; nt < 4; nt++)
#pragma unroll
            for (int i = 0; i < 4; i++) acc[mt][nt][i] = 0.0f;

    const int lrow = tid >> 1;
    const int lcol = (tid & 1) * 16;
    const float* ap = A  + (size_t)(m0 + lrow) * K + lcol;
    const float* bp = Bm + (size_t)(n0 + lrow) * K + lcol;

    float4 pa[4], pb[4];
#pragma unroll
    for (int i = 0; i < 4; i++) { pa[i] = *(const float4*)(ap + i * 4); pb[i] = *(const float4*)(bp + i * 4); }

    for (int k0 = 0; k0 < K; k0 += 32) {
#pragma unroll
        for (int i = 0; i < 4; i++) {
            float4 a = pa[i], b = pb[i];
            a.x = to_tf32(a.x); a.y = to_tf32(a.y); a.z = to_tf32(a.z); a.w = to_tf32(a.w);
            b.x = to_tf32(b.x); b.y = to_tf32(b.y); b.z = to_tf32(b.z); b.w = to_tf32(b.w);
            *(float4*)&As[lrow][lcol + i * 4] = a;
            *(float4*)&Bs[lrow][lcol + i * 4] = b;
        }
        __syncthreads();

        if (k0 + 32 < K) {
#pragma unroll
            for (int i = 0; i < 4; i++) {
                pa[i] = *(const float4*)(ap + k0 + 32 + i * 4);
                pb[i] = *(const float4*)(bp + k0 + 32 + i * 4);
            }
        }

#pragma unroll
        for (int kt = 0; kt < 4; kt++) {
            const int kc = kt * 8 + tg;
            unsigned fa[4][4], fb[4][2];
#pragma unroll
            for (int mt = 0; mt < 4; mt++) {
                const int r = wm + mt * 16 + g;
                fa[mt][0] = __float_as_uint(As[r][kc]);
                fa[mt][1] = __float_as_uint(As[r + 8][kc]);
                fa[mt][2] = __float_as_uint(As[r][kc + 4]);
                fa[mt][3] = __float_as_uint(As[r + 8][kc + 4]);
            }
#pragma unroll
            for (int nt = 0; nt < 4; nt++) {
                const int r = wn + nt * 8 + g;
                fb[nt][0] = __float_as_uint(Bs[r][kc]);
                fb[nt][1] = __float_as_uint(Bs[r][kc + 4]);
            }
#pragma unroll
            for (int mt = 0; mt < 4; mt++)
#pragma unroll
                for (int nt = 0; nt < 4; nt++)
                    mma_tf32(acc[mt][nt], fa[mt], fb[nt]);
        }
        __syncthreads();
    }

#pragma unroll
    for (int mt = 0; mt < 4; mt++) {
#pragma unroll
        for (int nt = 0; nt < 4; nt++) {
#pragma unroll
            for (int half = 0; half < 2; half++) {
                const int m = m0 + wm + mt * 16 + g + half * 8;
                const int n = n0 + wn + nt * 8 + tg * 2;
                float2 val = make_float2(acc[mt][nt][half * 2], acc[mt][nt][half * 2 + 1]);
                if (MODE == 0) {
                    const int b = m >> 11;
                    const int s = m & (SEQ - 1);
                    const int sel    = n >> 10;
                    const int within = n & (DIM - 1);
                    const int head   = within >> 6;
                    const int dcol   = within & (HD - 1);
                    const size_t idx = (((size_t)(b * NH + head) * SEQ) + s) * HD + dcol;
                    if (sel == 0)      *(float2*)&g_q[idx] = val;
                    else if (sel == 1) *(float2*)&g_k[idx] = val;
                    else               *(float2*)&g_v[idx] = val;
                } else {
                    *(float2*)&C[(size_t)m * Nld + n] = val;
                }
            }
        }
    }
}

// ---------------------------------------------------------------------------
// Flash attention (causal) on tensor cores.
// Q tile 128 (8 warps x 16 rows), K tile 32, hd=64.
// Q fragments register-resident across the whole k-loop.
// Softmax stats (m,l) register-resident per warp quad; no block sync in softmax.
// P round-trips through per-warp smem (C-frag -> A-frag relayout).
// ---------------------------------------------------------------------------
__global__ __launch_bounds__(256, 2) void attn_kernel() {
    __shared__ float Ks[32][68];   // [key][dim]   bank-clean for B-frag reads
    __shared__ float Vs[32][72];   // [key][dim]   stride 72 -> clean V^T frags
    __shared__ float Ss[128][36];  // P, per-warp 16-row regions

    const int tid  = threadIdx.x;
    const int warp = tid >> 5;
    const int lane = tid & 31;
    const int g    = lane >> 2;      // 0..7
    const int tg   = lane & 3;       // 0..3
    const int wm   = warp * 16;      // warp row offset in Q tile

    const int q0 = ((int)gridDim.x - 1 - (int)blockIdx.x) * 128;  // big tiles first
    const int bh = blockIdx.y;
    const int b  = bh >> 4;
    const int h  = bh & 15;

    const float* Qp = g_q + ((size_t)bh * SEQ + q0) * HD;
    const float* Kp = g_k + (size_t)bh * SEQ * HD;
    const float* Vp = g_v + (size_t)bh * SEQ * HD;

    // Q fragments: rows wm+g, wm+g+8; cols kt*8+tg, kt*8+tg+4  (tf32)
    unsigned qf[8][4];
#pragma unroll
    for (int kt = 0; kt < 8; kt++) {
        const int c = kt * 8 + tg;
        qf[kt][0] = to_tf32u(Qp[(size_t)(wm + g)     * HD + c]);
        qf[kt][1] = to_tf32u(Qp[(size_t)(wm + g + 8) * HD + c]);
        qf[kt][2] = to_tf32u(Qp[(size_t)(wm + g)     * HD + c + 4]);
        qf[kt][3] = to_tf32u(Qp[(size_t)(wm + g + 8) * HD + c + 4]);
    }

    float oacc[8][4];
#pragma unroll
    for (int nb = 0; nb < 8; nb++)
#pragma unroll
        for (int i = 0; i < 4; i++) oacc[nb][i] = 0.0f;

    float m0r = -1e30f, m1r = -1e30f, l0r = 0.0f, l1r = 0.0f;

    const int row0 = q0 + wm + g;
    const int row1 = row0 + 8;

    // K/V tile loader mapping: 32x64 floats, 8 per thread
    const int lrow = tid >> 3;           // 0..31
    const int lcol = (tid & 7) * 8;      // 0..56

    const int kend = q0 + 128;
    for (int k0 = 0; k0 < kend; k0 += 32) {
        __syncthreads();   // protect Ks/Vs/Ss from previous iteration readers
        {
            const float* kp = Kp + (size_t)(k0 + lrow) * HD + lcol;
            const float* vp = Vp + (size_t)(k0 + lrow) * HD + lcol;
#pragma unroll
            for (int i = 0; i < 2; i++) {
                float4 kv = *(const float4*)(kp + i * 4);
                float4 vv = *(const float4*)(vp + i * 4);
                kv.x = to_tf32(kv.x); kv.y = to_tf32(kv.y); kv.z = to_tf32(kv.z); kv.w = to_tf32(kv.w);
                vv.x = to_tf32(vv.x); vv.y = to_tf32(vv.y); vv.z = to_tf32(vv.z); vv.w = to_tf32(vv.w);
                *(float4*)&Ks[lrow][lcol + i * 4] = kv;
                *(float4*)&Vs[lrow][lcol + i * 4] = vv;
            }
        }
        __syncthreads();

        // S = Q @ K^T  (16 x 32 per warp)
        float sacc[4][4];
#pragma unroll
        for (int nb = 0; nb < 4; nb++)
#pragma unroll
            for (int i = 0; i < 4; i++) sacc[nb][i] = 0.0f;

#pragma unroll
        for (int kt = 0; kt < 8; kt++) {
            const int kc = kt * 8 + tg;
            unsigned bf[4][2];
#pragma unroll
            for (int nb = 0; nb < 4; nb++) {
                bf[nb][0] = __float_as_uint(Ks[nb * 8 + g][kc]);
                bf[nb][1] = __float_as_uint(Ks[nb * 8 + g][kc + 4]);
            }
#pragma unroll
            for (int nb = 0; nb < 4; nb++)
                mma_tf32(sacc[nb], qf[kt], bf[nb]);
        }

        // mask + scale (1/8)
#pragma unroll
        for (int nb = 0; nb < 4; nb++) {
#pragma unroll
            for (int j = 0; j < 2; j++) {
                const int col = k0 + nb * 8 + 2 * tg + j;
                sacc[nb][j]     = (col <= row0) ? sacc[nb][j]     * 0.125f : -1e30f;
                sacc[nb][2 + j] = (col <= row1) ? sacc[nb][2 + j] * 0.125f : -1e30f;
            }
        }

        // row max (quad reduce)
        float mx0 = -1e30f, mx1 = -1e30f;
#pragma unroll
        for (int nb = 0; nb < 4; nb++) {
            mx0 = fmaxf(mx0, fmaxf(sacc[nb][0], sacc[nb][1]));
            mx1 = fmaxf(mx1, fmaxf(sacc[nb][2], sacc[nb][3]));
        }
        mx0 = fmaxf(mx0, __shfl_xor_sync(0xffffffffu, mx0, 1));
        mx0 = fmaxf(mx0, __shfl_xor_sync(0xffffffffu, mx0, 2));
        mx1 = fmaxf(mx1, __shfl_xor_sync(0xffffffffu, mx1, 1));
        mx1 = fmaxf(mx1, __shfl_xor_sync(0xffffffffu, mx1, 2));

        const float mn0 = fmaxf(m0r, mx0);
        const float mn1 = fmaxf(m1r, mx1);
        const float sc0 = __expf(m0r - mn0);
        const float sc1 = __expf(m1r - mn1);

        // P = exp(S - m), write tf32 P to per-warp Ss region, accumulate l
        float ps0 = 0.0f, ps1 = 0.0f;
#pragma unroll
        for (int nb = 0; nb < 4; nb++) {
            const int cc = nb * 8 + 2 * tg;
            float p00 = __expf(sacc[nb][0] - mn0);
            float p01 = __expf(sacc[nb][1] - mn0);
            float p10 = __expf(sacc[nb][2] - mn1);
            float p11 = __expf(sacc[nb][3] - mn1);
            ps0 += p00 + p01;
            ps1 += p10 + p11;
            Ss[wm + g][cc]         = to_tf32(p00);
            Ss[wm + g][cc + 1]     = to_tf32(p01);
            Ss[wm + g + 8][cc]     = to_tf32(p10);
            Ss[wm + g + 8][cc + 1] = to_tf32(p11);
        }
        ps0 += __shfl_xor_sync(0xffffffffu, ps0, 1);
        ps0 += __shfl_xor_sync(0xffffffffu, ps0, 2);
        ps1 += __shfl_xor_sync(0xffffffffu, ps1, 1);
        ps1 += __shfl_xor_sync(0xffffffffu, ps1, 2);
        l0r = l0r * sc0 + ps0;
        l1r = l1r * sc1 + ps1;
        m0r = mn0;
        m1r = mn1;

        // rescale O
#pragma unroll
        for (int nb = 0; nb < 8; nb++) {
            oacc[nb][0] *= sc0; oacc[nb][1] *= sc0;
            oacc[nb][2] *= sc1; oacc[nb][3] *= sc1;
        }
        __syncwarp();   // Ss region is warp-private: warp-level sync suffices

        // O += P @ V   (A-frags from Ss, B-frags = V^T from Vs)
#pragma unroll
        for (int kt = 0; kt < 4; kt++) {
            const int kc = kt * 8 + tg;
            unsigned af[4];
            af[0] = __float_as_uint(Ss[wm + g][kc]);
            af[1] = __float_as_uint(Ss[wm + g + 8][kc]);
            af[2] = __float_as_uint(Ss[wm + g][kc + 4]);
            af[3] = __float_as_uint(Ss[wm + g + 8][kc + 4]);
#pragma unroll
            for (int nb = 0; nb < 8; nb++) {
                unsigned bf2[2];
                bf2[0] = __float_as_uint(Vs[kc][nb * 8 + g]);
                bf2[1] = __float_as_uint(Vs[kc + 4][nb * 8 + g]);
                mma_tf32(oacc[nb], af, bf2);
            }
        }
    }

    // epilogue: normalize and write [B,S,D]
    const float inv0 = 1.0f / l0r;
    const float inv1 = 1.0f / l1r;
    float* out0 = g_h + ((size_t)b * SEQ + row0) * DIM + h * HD;
    float* out1 = g_h + ((size_t)b * SEQ + row1) * DIM + h * HD;
#pragma unroll
    for (int nb = 0; nb < 8; nb++) {
        const int cc = nb * 8 + 2 * tg;
        *(float2*)(out0 + cc) = make_float2(oacc[nb][0] * inv0, oacc[nb][1] * inv0);
        *(float2*)(out1 + cc) = make_float2(oacc[nb][2] * inv1, oacc[nb][3] * inv1);
    }
}

// ---------------------------------------------------------------------------
extern "C" void kernel_launch(void* const* d_in, const int* in_sizes, int n_in,
                              void* d_out, int out_size) {
    const float* x     = (const float*)d_in[0];   // [B,S,D]
    const float* w_qkv = (const float*)d_in[1];   // [3D, D]
    const float* w_o   = (const float*)d_in[2];   // [D, D]
    float* out = (float*)d_out;                   // [B,S,D]

    // QKV projection: [4096,1024] @ [3072,1024]^T, scatter to q/k/v (tf32 mma)
    gemm_tf32<0><<<dim3(3 * DIM / 128, MROWS / 128), 256>>>(x, w_qkv, nullptr, DIM, 0);

    // Causal flash attention (tensor cores) -> g_h [B,S,D]
    attn_kernel<<<dim3(SEQ / 128, BATCH * NH), 256>>>();

    // Output projection: [4096,1024] @ [1024,1024]^T -> d_out (tf32 mma)
    float* hptr = nullptr;
    cudaGetSymbolAddress((void**)&hptr, g_h);
    gemm_tf32<1><<<dim3(DIM / 128, MROWS / 128), 256>>>(hptr, w_o, out, DIM, DIM);
}